// round 13
// baseline (speedup 1.0000x reference)
#include <cuda_runtime.h>
#include <math.h>

#define N_NODES 4096
#define N_EDGES 16384
#define D_IN    128
#define HID     1024

// ---------------- scratch (static device globals; no dynamic alloc) ----------
__device__ int   g_src[N_EDGES];
__device__ int   g_dst[N_EDGES];
__device__ float g_eH[N_NODES * D_IN];           // e[:,None]*H
__device__ float g_x0[N_NODES * 3 * D_IN];       // [Ho | H | Hi] concat, row stride 384
__device__ float g_x1[N_NODES * HID];
__device__ float g_x2[N_NODES * HID];
__device__ float g_x3[N_NODES * (HID / 2)];
__device__ float g_x4[N_NODES * (HID / 4)];

// ---------------- index extraction from dense one-hot rows -------------------
// One warp per row. Early-exit once any lane saw the (single) nonzero, so on
// average only half of each 16KB row is fetched from HBM.
__global__ void extract_idx_kernel(const float* __restrict__ R,
                                   int* __restrict__ out, int n_rows) {
    int warp = (blockIdx.x * blockDim.x + threadIdx.x) >> 5;
    int lane = threadIdx.x & 31;
    if (warp >= n_rows) return;
    const float4* row = (const float4*)(R + (size_t)warp * N_NODES);
    int found = -1;
    for (int i = lane; i < N_NODES / 4; i += 32) {
        float4 v = row[i];
        if (v.x != 0.f) found = i * 4 + 0;
        if (v.y != 0.f) found = i * 4 + 1;
        if (v.z != 0.f) found = i * 4 + 2;
        if (v.w != 0.f) found = i * 4 + 3;
        if (__ballot_sync(0xFFFFFFFFu, found >= 0)) break;
    }
#pragma unroll
    for (int o = 16; o; o >>= 1)
        found = max(found, __shfl_xor_sync(0xFFFFFFFFu, found, o));
    if (lane == 0) out[warp] = (found < 0) ? 0 : found;
}

// ---------------- eH compute + x0 init ---------------------------------------
__global__ void prep_kernel(const float* __restrict__ H, const float* __restrict__ e) {
    int idx = blockIdx.x * blockDim.x + threadIdx.x;   // 0 .. N*D-1
    if (idx >= N_NODES * D_IN) return;
    int n = idx >> 7, d = idx & 127;
    float h = H[idx];
    g_eH[idx] = e[n] * h;
    g_x0[(size_t)n * 384 + 128 + d] = h;   // middle block = H
    g_x0[(size_t)n * 384 + d]       = 0.f; // Ho accumulator
    g_x0[(size_t)n * 384 + 256 + d] = 0.f; // Hi accumulator
}

// ---------------- edge scatter-add -------------------------------------------
// Ho[n] = sum_{e: dst[e]==n} eH[src[e]] ; Hi[n] = sum_{e: src[e]==n} eH[dst[e]]
__global__ void scatter_kernel() {
    int eI   = (blockIdx.x * blockDim.x + threadIdx.x) >> 5;
    int lane = threadIdx.x & 31;
    if (eI >= N_EDGES) return;
    int s = g_src[eI], d = g_dst[eI];
    const float* es = g_eH + (size_t)s * 128;
    const float* ed = g_eH + (size_t)d * 128;
    float* ho = g_x0 + (size_t)d * 384;         // Ho block of node d
    float* hi = g_x0 + (size_t)s * 384 + 256;   // Hi block of node s
#pragma unroll
    for (int k = 0; k < 4; k++) {
        int dim = lane + k * 32;
        atomicAdd(ho + dim, es[dim]);
        atomicAdd(hi + dim, ed[dim]);
    }
}

// ---------------- accurate cheap tanh: 1 - 2/(1+e^{2x}) ----------------------
__device__ __forceinline__ float acc_tanh(float x) {
    x = fminf(fmaxf(x, -15.f), 15.f);
    float t = __expf(2.f * x);                 // MUFU.EX2, ~2^-22 rel err
    return 1.f - __fdividef(2.f, 1.f + t);     // MUFU.RCP, safe range here
}

// ---------------- 128x128x8 register-tiled SGEMM + bias + activation ----------
// C[M,N] = act(A[M,K] @ B[K,N] + bias).  Requires M%128==0, N%128==0, K%8==0.
template <int ACT>
__global__ void __launch_bounds__(256)
sgemm_kernel(const float* __restrict__ A, const float* __restrict__ B,
             const float* __restrict__ bias, float* __restrict__ C,
             int M, int N, int K) {
    __shared__ float As[8][128];
    __shared__ float Bs[8][128];
    const int tid = threadIdx.x;
    const int bm = blockIdx.y * 128, bn = blockIdx.x * 128;
    const int tx = tid & 15, ty = tid >> 4;          // 16x16 threads, 8x8 each
    const int aRow = tid >> 1, aCol = (tid & 1) * 4; // A tile load map
    const int bRow = tid >> 5, bCol = (tid & 31) * 4;// B tile load map

    const float* Aptr = A + (size_t)(bm + aRow) * K + aCol;
    const float* Bptr = B + (size_t)bRow * N + bn + bCol;

    float acc[8][8];
#pragma unroll
    for (int i = 0; i < 8; i++)
#pragma unroll
        for (int j = 0; j < 8; j++) acc[i][j] = 0.f;

    for (int k0 = 0; k0 < K; k0 += 8) {
        float4 av = *(const float4*)(Aptr + k0);
        float4 bv = *(const float4*)(Bptr + (size_t)k0 * N);
        As[aCol + 0][aRow] = av.x;
        As[aCol + 1][aRow] = av.y;
        As[aCol + 2][aRow] = av.z;
        As[aCol + 3][aRow] = av.w;
        *(float4*)&Bs[bRow][bCol] = bv;
        __syncthreads();
#pragma unroll
        for (int kk = 0; kk < 8; kk++) {
            float ar[8], br[8];
            *(float4*)&ar[0] = *(const float4*)&As[kk][ty * 4];
            *(float4*)&ar[4] = *(const float4*)&As[kk][64 + ty * 4];
            *(float4*)&br[0] = *(const float4*)&Bs[kk][tx * 4];
            *(float4*)&br[4] = *(const float4*)&Bs[kk][64 + tx * 4];
#pragma unroll
            for (int i = 0; i < 8; i++)
#pragma unroll
                for (int j = 0; j < 8; j++)
                    acc[i][j] += ar[i] * br[j];
        }
        __syncthreads();
    }

    // bias preload (two 4-col groups)
    float bb[8];
#pragma unroll
    for (int j = 0; j < 4; j++) {
        bb[j]     = bias[bn + tx * 4 + j];
        bb[4 + j] = bias[bn + 64 + tx * 4 + j];
    }

#pragma unroll
    for (int i = 0; i < 8; i++) {
        int r = bm + ((i < 4) ? (ty * 4 + i) : (64 + ty * 4 + (i - 4)));
        float4 v0, v1;
        float* pv0 = (float*)&v0;
        float* pv1 = (float*)&v1;
#pragma unroll
        for (int j = 0; j < 4; j++) {
            float a0 = acc[i][j] + bb[j];
            float a1 = acc[i][4 + j] + bb[4 + j];
            if (ACT) { a0 = acc_tanh(a0); a1 = acc_tanh(a1); }
            pv0[j] = a0; pv1[j] = a1;
        }
        *(float4*)&C[(size_t)r * N + bn + tx * 4]      = v0;
        *(float4*)&C[(size_t)r * N + bn + 64 + tx * 4] = v1;
    }
}

// ---------------- final layer: [4096,256] @ [256,1] + sigmoid ----------------
__global__ void final_kernel(const float* __restrict__ W5,
                             const float* __restrict__ b5,
                             float* __restrict__ out) {
    int row  = (blockIdx.x * blockDim.x + threadIdx.x) >> 5;
    int lane = threadIdx.x & 31;
    if (row >= N_NODES) return;
    const float4* xr = (const float4*)(g_x4 + (size_t)row * 256);
    const float4* wv = (const float4*)W5;
    float s = 0.f;
#pragma unroll
    for (int i = lane; i < 64; i += 32) {
        float4 a = xr[i], w = wv[i];
        s += a.x * w.x + a.y * w.y + a.z * w.z + a.w * w.w;
    }
#pragma unroll
    for (int o = 16; o; o >>= 1) s += __shfl_xor_sync(0xFFFFFFFFu, s, o);
    if (lane == 0) {
        float z = s + b5[0];
        z = fminf(fmaxf(z, -30.f), 30.f);
        out[row] = __fdividef(1.f, 1.f + __expf(-z));
    }
}

// ---------------- launcher ----------------------------------------------------
extern "C" void kernel_launch(void* const* d_in, const int* in_sizes, int n_in,
                              void* d_out, int out_size) {
    const float* H  = (const float*)d_in[0];
    const float* Ro = (const float*)d_in[1];
    const float* Ri = (const float*)d_in[2];
    const float* e  = (const float*)d_in[3];
    const float* W1 = (const float*)d_in[4];
    const float* b1 = (const float*)d_in[5];
    const float* W2 = (const float*)d_in[6];
    const float* b2 = (const float*)d_in[7];
    const float* W3 = (const float*)d_in[8];
    const float* b3 = (const float*)d_in[9];
    const float* W4 = (const float*)d_in[10];
    const float* b4 = (const float*)d_in[11];
    const float* W5 = (const float*)d_in[12];
    const float* b5 = (const float*)d_in[13];
    float* out = (float*)d_out;

    void* p;
    int *srcP, *dstP;
    float *x0, *x1, *x2, *x3, *x4;
    cudaGetSymbolAddress(&p, g_src); srcP = (int*)p;
    cudaGetSymbolAddress(&p, g_dst); dstP = (int*)p;
    cudaGetSymbolAddress(&p, g_x0); x0 = (float*)p;
    cudaGetSymbolAddress(&p, g_x1); x1 = (float*)p;
    cudaGetSymbolAddress(&p, g_x2); x2 = (float*)p;
    cudaGetSymbolAddress(&p, g_x3); x3 = (float*)p;
    cudaGetSymbolAddress(&p, g_x4); x4 = (float*)p;

    // 1) one-hot -> index extraction (memory-bound, early exit)
    extract_idx_kernel<<<2048, 256>>>(Ro, srcP, N_EDGES);
    extract_idx_kernel<<<2048, 256>>>(Ri, dstP, N_EDGES);
    // 2) eH + x0 init
    prep_kernel<<<2048, 256>>>(H, e);
    // 3) edge scatter-add into Ho/Hi blocks of x0
    scatter_kernel<<<2048, 256>>>();
    // 4) MLP
    sgemm_kernel<1><<<dim3(8, 32), 256>>>(x0, W1, b1, x1, N_NODES, HID,     3 * D_IN);
    sgemm_kernel<1><<<dim3(8, 32), 256>>>(x1, W2, b2, x2, N_NODES, HID,     HID);
    sgemm_kernel<1><<<dim3(4, 32), 256>>>(x2, W3, b3, x3, N_NODES, HID / 2, HID);
    sgemm_kernel<1><<<dim3(2, 32), 256>>>(x3, W4, b4, x4, N_NODES, HID / 4, HID / 2);
    // 5) final dot + sigmoid
    final_kernel<<<512, 256>>>(W5, b5, out);
}

// round 14
// speedup vs baseline: 1.0030x; 1.0030x over previous
#include <cuda_runtime.h>
#include <math.h>

#define N_NODES 4096
#define N_EDGES 16384
#define D_IN    128
#define HID     1024

// ---------------- scratch (static device globals; no dynamic alloc) ----------
__device__ int   g_src[N_EDGES];
__device__ int   g_dst[N_EDGES];
__device__ float g_eH[N_NODES * D_IN];           // e[:,None]*H
__device__ float g_x0[N_NODES * 3 * D_IN];       // [Ho | H | Hi] concat, row stride 384
__device__ float g_x1[N_NODES * HID];
__device__ float g_x2[N_NODES * HID];
__device__ float g_x3[N_NODES * (HID / 2)];
__device__ float g_x4[N_NODES * (HID / 4)];

// ---------------- index extraction from dense one-hot rows -------------------
// One warp per row. Early-exit once any lane saw the (single) nonzero, so on
// average only half of each 16KB row is fetched from HBM.
__global__ void extract_idx_kernel(const float* __restrict__ R,
                                   int* __restrict__ out, int n_rows) {
    int warp = (blockIdx.x * blockDim.x + threadIdx.x) >> 5;
    int lane = threadIdx.x & 31;
    if (warp >= n_rows) return;
    const float4* row = (const float4*)(R + (size_t)warp * N_NODES);
    int found = -1;
    for (int i = lane; i < N_NODES / 4; i += 32) {
        float4 v = row[i];
        if (v.x != 0.f) found = i * 4 + 0;
        if (v.y != 0.f) found = i * 4 + 1;
        if (v.z != 0.f) found = i * 4 + 2;
        if (v.w != 0.f) found = i * 4 + 3;
        if (__ballot_sync(0xFFFFFFFFu, found >= 0)) break;
    }
#pragma unroll
    for (int o = 16; o; o >>= 1)
        found = max(found, __shfl_xor_sync(0xFFFFFFFFu, found, o));
    if (lane == 0) out[warp] = (found < 0) ? 0 : found;
}

// ---------------- eH compute + x0 init ---------------------------------------
__global__ void prep_kernel(const float* __restrict__ H, const float* __restrict__ e) {
    int idx = blockIdx.x * blockDim.x + threadIdx.x;   // 0 .. N*D-1
    if (idx >= N_NODES * D_IN) return;
    int n = idx >> 7, d = idx & 127;
    float h = H[idx];
    g_eH[idx] = e[n] * h;
    g_x0[(size_t)n * 384 + 128 + d] = h;   // middle block = H
    g_x0[(size_t)n * 384 + d]       = 0.f; // Ho accumulator
    g_x0[(size_t)n * 384 + 256 + d] = 0.f; // Hi accumulator
}

// ---------------- edge scatter-add -------------------------------------------
// Ho[n] = sum_{e: dst[e]==n} eH[src[e]] ; Hi[n] = sum_{e: src[e]==n} eH[dst[e]]
__global__ void scatter_kernel() {
    int eI   = (blockIdx.x * blockDim.x + threadIdx.x) >> 5;
    int lane = threadIdx.x & 31;
    if (eI >= N_EDGES) return;
    int s = g_src[eI], d = g_dst[eI];
    const float* es = g_eH + (size_t)s * 128;
    const float* ed = g_eH + (size_t)d * 128;
    float* ho = g_x0 + (size_t)d * 384;         // Ho block of node d
    float* hi = g_x0 + (size_t)s * 384 + 256;   // Hi block of node s
#pragma unroll
    for (int k = 0; k < 4; k++) {
        int dim = lane + k * 32;
        atomicAdd(ho + dim, es[dim]);
        atomicAdd(hi + dim, ed[dim]);
    }
}

// ---------------- accurate cheap tanh: 1 - 2/(1+e^{2x}) ----------------------
__device__ __forceinline__ float acc_tanh(float x) {
    x = fminf(fmaxf(x, -15.f), 15.f);
    float t = __expf(2.f * x);                 // MUFU.EX2, ~2^-22 rel err
    return 1.f - __fdividef(2.f, 1.f + t);     // MUFU.RCP, safe range here
}

// ---------------- 128x128x8 register-tiled SGEMM + bias + activation ----------
// C[M,N] = act(A[M,K] @ B[K,N] + bias).  Requires M%128==0, N%128==0, K%8==0.
template <int ACT>
__global__ void __launch_bounds__(256)
sgemm_kernel(const float* __restrict__ A, const float* __restrict__ B,
             const float* __restrict__ bias, float* __restrict__ C,
             int M, int N, int K) {
    __shared__ float As[8][128];
    __shared__ float Bs[8][128];
    const int tid = threadIdx.x;
    const int bm = blockIdx.y * 128, bn = blockIdx.x * 128;
    const int tx = tid & 15, ty = tid >> 4;          // 16x16 threads, 8x8 each
    const int aRow = tid >> 1, aCol = (tid & 1) * 4; // A tile load map
    const int bRow = tid >> 5, bCol = (tid & 31) * 4;// B tile load map

    const float* Aptr = A + (size_t)(bm + aRow) * K + aCol;
    const float* Bptr = B + (size_t)bRow * N + bn + bCol;

    float acc[8][8];
#pragma unroll
    for (int i = 0; i < 8; i++)
#pragma unroll
        for (int j = 0; j < 8; j++) acc[i][j] = 0.f;

    for (int k0 = 0; k0 < K; k0 += 8) {
        float4 av = *(const float4*)(Aptr + k0);
        float4 bv = *(const float4*)(Bptr + (size_t)k0 * N);
        As[aCol + 0][aRow] = av.x;
        As[aCol + 1][aRow] = av.y;
        As[aCol + 2][aRow] = av.z;
        As[aCol + 3][aRow] = av.w;
        *(float4*)&Bs[bRow][bCol] = bv;
        __syncthreads();
#pragma unroll
        for (int kk = 0; kk < 8; kk++) {
            float ar[8], br[8];
            *(float4*)&ar[0] = *(const float4*)&As[kk][ty * 4];
            *(float4*)&ar[4] = *(const float4*)&As[kk][64 + ty * 4];
            *(float4*)&br[0] = *(const float4*)&Bs[kk][tx * 4];
            *(float4*)&br[4] = *(const float4*)&Bs[kk][64 + tx * 4];
#pragma unroll
            for (int i = 0; i < 8; i++)
#pragma unroll
                for (int j = 0; j < 8; j++)
                    acc[i][j] += ar[i] * br[j];
        }
        __syncthreads();
    }

    // bias preload (two 4-col groups)
    float bb[8];
#pragma unroll
    for (int j = 0; j < 4; j++) {
        bb[j]     = bias[bn + tx * 4 + j];
        bb[4 + j] = bias[bn + 64 + tx * 4 + j];
    }

#pragma unroll
    for (int i = 0; i < 8; i++) {
        int r = bm + ((i < 4) ? (ty * 4 + i) : (64 + ty * 4 + (i - 4)));
        float4 v0, v1;
        float* pv0 = (float*)&v0;
        float* pv1 = (float*)&v1;
#pragma unroll
        for (int j = 0; j < 4; j++) {
            float a0 = acc[i][j] + bb[j];
            float a1 = acc[i][4 + j] + bb[4 + j];
            if (ACT) { a0 = acc_tanh(a0); a1 = acc_tanh(a1); }
            pv0[j] = a0; pv1[j] = a1;
        }
        *(float4*)&C[(size_t)r * N + bn + tx * 4]      = v0;
        *(float4*)&C[(size_t)r * N + bn + 64 + tx * 4] = v1;
    }
}

// ---------------- final layer: [4096,256] @ [256,1] + sigmoid ----------------
__global__ void final_kernel(const float* __restrict__ W5,
                             const float* __restrict__ b5,
                             float* __restrict__ out) {
    int row  = (blockIdx.x * blockDim.x + threadIdx.x) >> 5;
    int lane = threadIdx.x & 31;
    if (row >= N_NODES) return;
    const float4* xr = (const float4*)(g_x4 + (size_t)row * 256);
    const float4* wv = (const float4*)W5;
    float s = 0.f;
#pragma unroll
    for (int i = lane; i < 64; i += 32) {
        float4 a = xr[i], w = wv[i];
        s += a.x * w.x + a.y * w.y + a.z * w.z + a.w * w.w;
    }
#pragma unroll
    for (int o = 16; o; o >>= 1) s += __shfl_xor_sync(0xFFFFFFFFu, s, o);
    if (lane == 0) {
        float z = s + b5[0];
        z = fminf(fmaxf(z, -30.f), 30.f);
        out[row] = __fdividef(1.f, 1.f + __expf(-z));
    }
}

// ---------------- launcher ----------------------------------------------------
extern "C" void kernel_launch(void* const* d_in, const int* in_sizes, int n_in,
                              void* d_out, int out_size) {
    const float* H  = (const float*)d_in[0];
    const float* Ro = (const float*)d_in[1];
    const float* Ri = (const float*)d_in[2];
    const float* e  = (const float*)d_in[3];
    const float* W1 = (const float*)d_in[4];
    const float* b1 = (const float*)d_in[5];
    const float* W2 = (const float*)d_in[6];
    const float* b2 = (const float*)d_in[7];
    const float* W3 = (const float*)d_in[8];
    const float* b3 = (const float*)d_in[9];
    const float* W4 = (const float*)d_in[10];
    const float* b4 = (const float*)d_in[11];
    const float* W5 = (const float*)d_in[12];
    const float* b5 = (const float*)d_in[13];
    float* out = (float*)d_out;

    void* p;
    int *srcP, *dstP;
    float *x0, *x1, *x2, *x3, *x4;
    cudaGetSymbolAddress(&p, g_src); srcP = (int*)p;
    cudaGetSymbolAddress(&p, g_dst); dstP = (int*)p;
    cudaGetSymbolAddress(&p, g_x0); x0 = (float*)p;
    cudaGetSymbolAddress(&p, g_x1); x1 = (float*)p;
    cudaGetSymbolAddress(&p, g_x2); x2 = (float*)p;
    cudaGetSymbolAddress(&p, g_x3); x3 = (float*)p;
    cudaGetSymbolAddress(&p, g_x4); x4 = (float*)p;

    // 1) one-hot -> index extraction (memory-bound, early exit)
    extract_idx_kernel<<<2048, 256>>>(Ro, srcP, N_EDGES);
    extract_idx_kernel<<<2048, 256>>>(Ri, dstP, N_EDGES);
    // 2) eH + x0 init
    prep_kernel<<<2048, 256>>>(H, e);
    // 3) edge scatter-add into Ho/Hi blocks of x0
    scatter_kernel<<<2048, 256>>>();
    // 4) MLP
    sgemm_kernel<1><<<dim3(8, 32), 256>>>(x0, W1, b1, x1, N_NODES, HID,     3 * D_IN);
    sgemm_kernel<1><<<dim3(8, 32), 256>>>(x1, W2, b2, x2, N_NODES, HID,     HID);
    sgemm_kernel<1><<<dim3(4, 32), 256>>>(x2, W3, b3, x3, N_NODES, HID / 2, HID);
    sgemm_kernel<1><<<dim3(2, 32), 256>>>(x3, W4, b4, x4, N_NODES, HID / 4, HID / 2);
    // 5) final dot + sigmoid
    final_kernel<<<512, 256>>>(W5, b5, out);
}